// round 2
// baseline (speedup 1.0000x reference)
#include <cuda_runtime.h>
#include <cuda_bf16.h>
#include <cstdint>
#include <math.h>

// Problem dims (fixed by the dataset)
#define MM 32768      // B*S
#define HH 1024
#define II 4096
#define LN_EPS 1e-5f

// Scratch (device globals: allocation-free rule)
__device__ float g_resadd[(size_t)MM * HH];   // 128 MB
__device__ float g_x[(size_t)MM * HH];        // 128 MB
__device__ float g_h[(size_t)MM * II];        // 512 MB

// ---------------------------------------------------------------------------
// Kernel 1: residual_add = input + bias + residual ; x = LN(residual_add)*g+b
// one block per row of H=1024, 256 threads, 1 float4 per thread
// ---------------------------------------------------------------------------
__global__ void __launch_bounds__(256) fused_add_ln_kernel(
    const float* __restrict__ inp, const float* __restrict__ resid,
    const float* __restrict__ bias, const float* __restrict__ gamma,
    const float* __restrict__ beta)
{
    const int row = blockIdx.x;
    const int t = threadIdx.x;
    const size_t base = (size_t)row * HH;

    float4 v = ((const float4*)(inp + base))[t];
    float4 r = ((const float4*)(resid + base))[t];
    float4 b = ((const float4*)bias)[t];
    v.x += b.x + r.x; v.y += b.y + r.y; v.z += b.z + r.z; v.w += b.w + r.w;
    ((float4*)(g_resadd + base))[t] = v;

    float s  = v.x + v.y + v.z + v.w;
    float sq = v.x*v.x + v.y*v.y + v.z*v.z + v.w*v.w;
    #pragma unroll
    for (int o = 16; o > 0; o >>= 1) {
        s  += __shfl_xor_sync(0xffffffffu, s,  o);
        sq += __shfl_xor_sync(0xffffffffu, sq, o);
    }
    __shared__ float sh_s[8], sh_q[8];
    const int warp = t >> 5, lane = t & 31;
    if (lane == 0) { sh_s[warp] = s; sh_q[warp] = sq; }
    __syncthreads();
    s = 0.f; sq = 0.f;
    #pragma unroll
    for (int i = 0; i < 8; i++) { s += sh_s[i]; sq += sh_q[i]; }

    const float mu   = s * (1.0f / HH);
    const float var  = sq * (1.0f / HH) - mu * mu;
    const float rstd = rsqrtf(var + LN_EPS);

    float4 gm = ((const float4*)gamma)[t];
    float4 bt = ((const float4*)beta)[t];
    v.x = (v.x - mu) * rstd * gm.x + bt.x;
    v.y = (v.y - mu) * rstd * gm.y + bt.y;
    v.z = (v.z - mu) * rstd * gm.z + bt.z;
    v.w = (v.w - mu) * rstd * gm.w + bt.w;
    ((float4*)(g_x + base))[t] = v;
}

// ---------------------------------------------------------------------------
// TF32 mma.sync GEMM: C[M,N] = A[M,K] @ B[K,N] (+ epilogue)
// Block tile 128x128, BK=16, 256 threads, 8 warps (4 along M x 2 along N),
// warp tile 32x64, double-buffered smem.
// EPI==0: C = gelu_tanh(acc + bias[n])        (GEMM1 -> g_h)
// EPI==1: C = acc + bias[n] + add[m*N+n]      (GEMM2 -> d_out)
// ---------------------------------------------------------------------------
#define BM 128
#define BN 128
#define BK 16
#define SA 20    // As row stride (BK + 4): frag banks g*20+tig all distinct
#define SB 136   // Bs row stride (BN + 8): frag banks tig*8+g all distinct

__device__ __forceinline__ float to_tf32(float x) {
    uint32_t u;
    asm("cvt.rna.tf32.f32 %0, %1;" : "=r"(u) : "f"(x));
    return __uint_as_float(u);
}

__device__ __forceinline__ void mma_tf32(float c[4],
    uint32_t a0, uint32_t a1, uint32_t a2, uint32_t a3,
    uint32_t b0, uint32_t b1)
{
    asm volatile(
        "mma.sync.aligned.m16n8k8.row.col.f32.tf32.tf32.f32 "
        "{%0,%1,%2,%3}, {%4,%5,%6,%7}, {%8,%9}, {%0,%1,%2,%3};\n"
        : "+f"(c[0]), "+f"(c[1]), "+f"(c[2]), "+f"(c[3])
        : "r"(a0), "r"(a1), "r"(a2), "r"(a3), "r"(b0), "r"(b1));
}

__device__ __forceinline__ float gelu_tanh(float x) {
    float x3 = x * x * x;
    return 0.5f * x * (1.0f + tanhf(0.7978845608028654f * (x + 0.044715f * x3)));
}

template <int EPI>
__global__ void __launch_bounds__(256, 1) gemm_tf32_kernel(
    const float* __restrict__ A, const float* __restrict__ B,
    const float* __restrict__ bias, const float* __restrict__ add,
    float* __restrict__ C, int K, int N)
{
    __shared__ float As[2][BM][SA];
    __shared__ float Bs[2][BK][SB];

    const int t = threadIdx.x;
    const int bn = blockIdx.x, bm = blockIdx.y;
    const int lane = t & 31, warp = t >> 5;
    const int g = lane >> 2, tig = lane & 3;
    const int wm = (warp & 3) * 32;   // warp row offset within block tile
    const int wn = (warp >> 2) * 64;  // warp col offset within block tile

    float acc[2][8][4];
    #pragma unroll
    for (int i = 0; i < 2; i++)
        #pragma unroll
        for (int j = 0; j < 8; j++)
            #pragma unroll
            for (int l = 0; l < 4; l++) acc[i][j][l] = 0.f;

    // global->reg staging layout
    // A tile: 128 rows x 16 cols = 512 float4; thread handles idx t, t+256
    const int ar0 = t >> 2, ac = (t & 3) * 4;          // ar in {0..63} then +64
    // B tile: 16 rows x 128 cols = 512 float4
    const int br0 = t >> 5, bc = (t & 31) * 4;         // br in {0..7} then +8

    const int ktiles = K / BK;
    float4 ra[2], rb[2];

    // prologue: tile 0
    {
        const float* Ap = A + (size_t)(bm * BM) * K;
        ra[0] = *(const float4*)(Ap + (size_t)ar0 * K + ac);
        ra[1] = *(const float4*)(Ap + (size_t)(ar0 + 64) * K + ac);
        const float* Bp = B + (size_t)bn * BN;
        rb[0] = *(const float4*)(Bp + (size_t)br0 * N + bc);
        rb[1] = *(const float4*)(Bp + (size_t)(br0 + 8) * N + bc);
        #pragma unroll
        for (int i = 0; i < 2; i++) {
            float4 v = ra[i];
            v.x = to_tf32(v.x); v.y = to_tf32(v.y); v.z = to_tf32(v.z); v.w = to_tf32(v.w);
            *(float4*)&As[0][ar0 + 64 * i][ac] = v;
            float4 w = rb[i];
            w.x = to_tf32(w.x); w.y = to_tf32(w.y); w.z = to_tf32(w.z); w.w = to_tf32(w.w);
            *(float4*)&Bs[0][br0 + 8 * i][bc] = w;
        }
    }
    __syncthreads();

    int buf = 0;
    for (int kt = 0; kt < ktiles; kt++) {
        const bool has_next = (kt + 1 < ktiles);
        if (has_next) {
            const int k0 = (kt + 1) * BK;
            const float* Ap = A + (size_t)(bm * BM) * K + k0;
            ra[0] = *(const float4*)(Ap + (size_t)ar0 * K + ac);
            ra[1] = *(const float4*)(Ap + (size_t)(ar0 + 64) * K + ac);
            const float* Bp = B + (size_t)k0 * N + (size_t)bn * BN;
            rb[0] = *(const float4*)(Bp + (size_t)br0 * N + bc);
            rb[1] = *(const float4*)(Bp + (size_t)(br0 + 8) * N + bc);
        }

        // compute on smem[buf]
        #pragma unroll
        for (int ks = 0; ks < BK / 8; ks++) {
            const int k0 = ks * 8;
            uint32_t af[2][4];
            #pragma unroll
            for (int mt = 0; mt < 2; mt++) {
                const int m = wm + mt * 16;
                af[mt][0] = __float_as_uint(As[buf][m + g][k0 + tig]);
                af[mt][1] = __float_as_uint(As[buf][m + g + 8][k0 + tig]);
                af[mt][2] = __float_as_uint(As[buf][m + g][k0 + tig + 4]);
                af[mt][3] = __float_as_uint(As[buf][m + g + 8][k0 + tig + 4]);
            }
            uint32_t bf[8][2];
            #pragma unroll
            for (int nt = 0; nt < 8; nt++) {
                const int n = wn + nt * 8 + g;
                bf[nt][0] = __float_as_uint(Bs[buf][k0 + tig][n]);
                bf[nt][1] = __float_as_uint(Bs[buf][k0 + tig + 4][n]);
            }
            #pragma unroll
            for (int mt = 0; mt < 2; mt++)
                #pragma unroll
                for (int nt = 0; nt < 8; nt++)
                    mma_tf32(acc[mt][nt], af[mt][0], af[mt][1], af[mt][2], af[mt][3],
                             bf[nt][0], bf[nt][1]);
        }

        if (has_next) {
            const int nbuf = buf ^ 1;
            #pragma unroll
            for (int i = 0; i < 2; i++) {
                float4 v = ra[i];
                v.x = to_tf32(v.x); v.y = to_tf32(v.y); v.z = to_tf32(v.z); v.w = to_tf32(v.w);
                *(float4*)&As[nbuf][ar0 + 64 * i][ac] = v;
                float4 w = rb[i];
                w.x = to_tf32(w.x); w.y = to_tf32(w.y); w.z = to_tf32(w.z); w.w = to_tf32(w.w);
                *(float4*)&Bs[nbuf][br0 + 8 * i][bc] = w;
            }
            __syncthreads();
            buf = nbuf;
        }
    }

    // epilogue
    #pragma unroll
    for (int mt = 0; mt < 2; mt++) {
        const int r0 = bm * BM + wm + mt * 16 + g;
        #pragma unroll
        for (int nt = 0; nt < 8; nt++) {
            const int c = bn * BN + wn + nt * 8 + (tig << 1);
            const float b0 = __ldg(bias + c);
            const float b1 = __ldg(bias + c + 1);
            float* p0 = C + (size_t)r0 * N + c;
            float* p1 = C + (size_t)(r0 + 8) * N + c;
            if (EPI == 0) {
                float2 v0, v1;
                v0.x = gelu_tanh(acc[mt][nt][0] + b0);
                v0.y = gelu_tanh(acc[mt][nt][1] + b1);
                v1.x = gelu_tanh(acc[mt][nt][2] + b0);
                v1.y = gelu_tanh(acc[mt][nt][3] + b1);
                *(float2*)p0 = v0;
                *(float2*)p1 = v1;
            } else {
                const float* a0 = add + (size_t)r0 * N + c;
                const float* a1 = add + (size_t)(r0 + 8) * N + c;
                float2 r0v = *(const float2*)a0;
                float2 r1v = *(const float2*)a1;
                float2 v0, v1;
                v0.x = acc[mt][nt][0] + b0 + r0v.x;
                v0.y = acc[mt][nt][1] + b1 + r0v.y;
                v1.x = acc[mt][nt][2] + b0 + r1v.x;
                v1.y = acc[mt][nt][3] + b1 + r1v.y;
                *(float2*)p0 = v0;
                *(float2*)p1 = v1;
            }
        }
    }
}

// ---------------------------------------------------------------------------
extern "C" void kernel_launch(void* const* d_in, const int* in_sizes, int n_in,
                              void* d_out, int out_size)
{
    const float* input    = (const float*)d_in[0];
    const float* residual = (const float*)d_in[1];
    // d_in[2] = residual_norm (unused by the reference computation)
    const float* bias     = (const float*)d_in[3];
    const float* attn_nw  = (const float*)d_in[4];
    const float* attn_nb  = (const float*)d_in[5];
    const float* inter_w  = (const float*)d_in[6];
    const float* inter_b  = (const float*)d_in[7];
    const float* output_w = (const float*)d_in[8];
    const float* output_b = (const float*)d_in[9];
    float* out = (float*)d_out;

    float *p_resadd, *p_x, *p_h;
    cudaGetSymbolAddress((void**)&p_resadd, g_resadd);
    cudaGetSymbolAddress((void**)&p_x, g_x);
    cudaGetSymbolAddress((void**)&p_h, g_h);

    // 1) fused bias+residual add + LayerNorm
    fused_add_ln_kernel<<<MM, 256>>>(input, residual, bias, attn_nw, attn_nb);

    // 2) h = gelu(x @ inter_w + inter_b)   [32768 x 4096]
    dim3 grid1(II / BN, MM / BM);
    gemm_tf32_kernel<0><<<grid1, 256>>>(p_x, inter_w, inter_b, nullptr, p_h, HH, II);

    // 3) out = h @ output_w + output_b + residual_add   [32768 x 1024]
    dim3 grid2(HH / BN, MM / BM);
    gemm_tf32_kernel<1><<<grid2, 256>>>(p_h, output_w, output_b, p_resadd, out, II, HH);
}

// round 10
// speedup vs baseline: 2.1880x; 2.1880x over previous
#include <cuda_runtime.h>
#include <cuda_fp16.h>
#include <cstdint>
#include <math.h>

// Problem dims (fixed by the dataset)
#define MM 32768      // B*S
#define HH 1024
#define II 4096
#define LN_EPS 1e-5f

// Scratch (device globals: allocation-free rule)
__device__ float  g_resadd[(size_t)MM * HH];   // 128 MB fp32 pre-norm sum
__device__ __half g_xh[(size_t)MM * HH];       // 64 MB  fp16 LN output
__device__ __half g_h[(size_t)MM * II];        // 256 MB fp16 gelu output
__device__ __half g_w1h[(size_t)HH * II];      // 8 MB   inter_w  [H,I] fp16 (row-major K,N)
__device__ __half g_w2h[(size_t)II * HH];      // 8 MB   output_w [I,H] fp16 (row-major K,N)

// ---------------------------------------------------------------------------
// helpers
// ---------------------------------------------------------------------------
__device__ __forceinline__ uint32_t smem_u32(const void* p) {
    uint32_t a;
    asm("{ .reg .u64 t; cvta.to.shared.u64 t, %1; cvt.u32.u64 %0, t; }" : "=r"(a) : "l"(p));
    return a;
}
__device__ __forceinline__ float tanh_fast(float x) {
    float y;
    asm("tanh.approx.f32 %0, %1;" : "=f"(y) : "f"(x));
    return y;
}
__device__ __forceinline__ float gelu_tanh(float x) {
    float x3 = x * x * x;
    return 0.5f * x * (1.0f + tanh_fast(0.7978845608028654f * (x + 0.044715f * x3)));
}
__device__ __forceinline__ uint32_t h2_as_u32(__half2 h) {
    uint32_t u;
    *(__half2*)&u = h;
    return u;
}

#define CP_ASYNC16(dst, src) \
    asm volatile("cp.async.cg.shared.global [%0], [%1], 16;\n" :: "r"(dst), "l"(src) : "memory")
#define CP_COMMIT() asm volatile("cp.async.commit_group;\n" ::: "memory")
#define CP_WAIT2()  asm volatile("cp.async.wait_group 2;\n" ::: "memory")

#define LDSM_X4(r, addr) \
    asm volatile("ldmatrix.sync.aligned.m8n8.x4.shared.b16 {%0,%1,%2,%3}, [%4];" \
        : "=r"((r)[0]), "=r"((r)[1]), "=r"((r)[2]), "=r"((r)[3]) : "r"(addr))
#define LDSM_X4T(r, addr) \
    asm volatile("ldmatrix.sync.aligned.m8n8.x4.trans.shared.b16 {%0,%1,%2,%3}, [%4];" \
        : "=r"((r)[0]), "=r"((r)[1]), "=r"((r)[2]), "=r"((r)[3]) : "r"(addr))

__device__ __forceinline__ void mma_f16(float c[4], const uint32_t a[4],
                                        uint32_t b0, uint32_t b1) {
    asm volatile(
        "mma.sync.aligned.m16n8k16.row.col.f32.f16.f16.f32 "
        "{%0,%1,%2,%3}, {%4,%5,%6,%7}, {%8,%9}, {%0,%1,%2,%3};\n"
        : "+f"(c[0]), "+f"(c[1]), "+f"(c[2]), "+f"(c[3])
        : "r"(a[0]), "r"(a[1]), "r"(a[2]), "r"(a[3]), "r"(b0), "r"(b1));
}

// ---------------------------------------------------------------------------
// Kernel 1: resadd = input + bias + residual ; x = fp16(LN(resadd)*g + b)
// ---------------------------------------------------------------------------
__global__ void __launch_bounds__(256) fused_add_ln_kernel(
    const float* __restrict__ inp, const float* __restrict__ resid,
    const float* __restrict__ bias, const float* __restrict__ gamma,
    const float* __restrict__ beta)
{
    const int row = blockIdx.x;
    const int t = threadIdx.x;
    const size_t base = (size_t)row * HH;

    float4 v = ((const float4*)(inp + base))[t];
    float4 r = ((const float4*)(resid + base))[t];
    float4 b = ((const float4*)bias)[t];
    v.x += b.x + r.x; v.y += b.y + r.y; v.z += b.z + r.z; v.w += b.w + r.w;
    ((float4*)(g_resadd + base))[t] = v;

    float s  = v.x + v.y + v.z + v.w;
    float sq = v.x*v.x + v.y*v.y + v.z*v.z + v.w*v.w;
    #pragma unroll
    for (int o = 16; o > 0; o >>= 1) {
        s  += __shfl_xor_sync(0xffffffffu, s,  o);
        sq += __shfl_xor_sync(0xffffffffu, sq, o);
    }
    __shared__ float sh_s[8], sh_q[8];
    const int warp = t >> 5, lane = t & 31;
    if (lane == 0) { sh_s[warp] = s; sh_q[warp] = sq; }
    __syncthreads();
    s = 0.f; sq = 0.f;
    #pragma unroll
    for (int i = 0; i < 8; i++) { s += sh_s[i]; sq += sh_q[i]; }

    const float mu   = s * (1.0f / HH);
    const float var  = sq * (1.0f / HH) - mu * mu;
    const float rstd = rsqrtf(var + LN_EPS);

    float4 gm = ((const float4*)gamma)[t];
    float4 bt = ((const float4*)beta)[t];
    __half2 h0 = __floats2half2_rn((v.x - mu) * rstd * gm.x + bt.x,
                                   (v.y - mu) * rstd * gm.y + bt.y);
    __half2 h1 = __floats2half2_rn((v.z - mu) * rstd * gm.z + bt.z,
                                   (v.w - mu) * rstd * gm.w + bt.w);
    uint2 pk;
    pk.x = h2_as_u32(h0);
    pk.y = h2_as_u32(h1);
    ((uint2*)(g_xh + base))[t] = pk;
}

// ---------------------------------------------------------------------------
// fp32 -> fp16 elementwise convert (weights)
// ---------------------------------------------------------------------------
__global__ void __launch_bounds__(256) f2h_kernel(
    const float* __restrict__ src, __half* __restrict__ dst, int n4)
{
    const int i = blockIdx.x * 256 + threadIdx.x;
    if (i < n4) {
        float4 v = ((const float4*)src)[i];
        uint2 pk;
        pk.x = h2_as_u32(__floats2half2_rn(v.x, v.y));
        pk.y = h2_as_u32(__floats2half2_rn(v.z, v.w));
        ((uint2*)dst)[i] = pk;
    }
}

// ---------------------------------------------------------------------------
// fp16 mma.sync GEMM: C[M,N] = A[M,K] @ B[K,N] (+ epilogue)
// Block tile 128x128, BK=32, 256 threads, 8 warps (4M x 2N), warp tile 32x64.
// 4-stage cp.async pipeline; ldmatrix-fed fragments; fp32 accumulate.
// EPI==0: C(fp16) = gelu(acc + bias[n])
// EPI==1: C(fp32) = acc + bias[n] + resadd[m,n]
// ---------------------------------------------------------------------------
#define BM 128
#define BN 128
#define BK 32
#define STAGES 4
#define A_ROWB 80                    // 32 halves = 64B data + 16B pad
#define B_ROWB 272                   // 128 halves = 256B data + 16B pad
#define A_BYTES (BM * A_ROWB)        // 10240
#define B_BYTES (BK * B_ROWB)        // 8704
#define STAGE_BYTES (A_BYTES + B_BYTES)   // 18944
#define DSMEM_BYTES (STAGES * STAGE_BYTES)

template <int EPI>
__global__ void __launch_bounds__(256, 1) gemm_f16_kernel(
    const __half* __restrict__ A, const __half* __restrict__ B,
    const float* __restrict__ bias, const float* __restrict__ add,
    void* __restrict__ Cv, int K, int N)
{
    extern __shared__ __align__(128) char dsm[];
    const uint32_t smem = smem_u32(dsm);

    const int t = threadIdx.x;
    const int wid = t >> 5, lane = t & 31;
    const int m0 = blockIdx.y * BM, n0 = blockIdx.x * BN;
    const int wm = (wid & 3) * 32;   // warp row offset
    const int wn = (wid >> 2) * 64;  // warp col offset
    const int KT = K / BK;

    float acc[2][8][4];
    #pragma unroll
    for (int i = 0; i < 2; i++)
        #pragma unroll
        for (int j = 0; j < 8; j++)
            #pragma unroll
            for (int l = 0; l < 4; l++) acc[i][j][l] = 0.f;

    // cp.async staging indices
    const int a_row = t >> 1, a_c = t & 1;        // A: 128 rows x 4 chunks
    const int b_row = t >> 4, b_c = t & 15;       // B: 32 rows x 16 chunks

    auto load_tile = [&](int kt, int stage) {
        const uint32_t abuf = smem + stage * STAGE_BYTES;
        const uint32_t bbuf = abuf + A_BYTES;
        const int k0 = kt * BK;
        // A: 512 chunks of 16B
        #pragma unroll
        for (int j = 0; j < 2; j++) {
            const int c = a_c * 2 + j;
            const uint32_t dst = abuf + a_row * A_ROWB + c * 16;
            const __half* src = A + (size_t)(m0 + a_row) * K + k0 + c * 8;
            CP_ASYNC16(dst, src);
        }
        // B: 512 chunks
        #pragma unroll
        for (int j = 0; j < 2; j++) {
            const int rr = b_row + j * 16;
            const uint32_t dst = bbuf + rr * B_ROWB + b_c * 16;
            const __half* src = B + (size_t)(k0 + rr) * N + n0 + b_c * 8;
            CP_ASYNC16(dst, src);
        }
    };

    // prologue: stages 0..2
    #pragma unroll
    for (int kt = 0; kt < 3; kt++) {
        if (kt < KT) load_tile(kt, kt);
        CP_COMMIT();
    }

    // per-lane ldmatrix base offsets
    const int lrow = lane & 15;          // row within 16-row group
    const int lcol8 = (lane >> 4) * 8;   // 0 or 8 (halves)

    for (int kt = 0; kt < KT; kt++) {
        const int s = kt & 3;
        CP_WAIT2();
        __syncthreads();

        // prefetch tile kt+3 into stage (kt+3)&3 (freed: compute kt-1 done)
        if (kt + 3 < KT) load_tile(kt + 3, (kt + 3) & 3);
        CP_COMMIT();

        const uint32_t abuf = smem + s * STAGE_BYTES;
        const uint32_t bbuf = abuf + A_BYTES;
        const uint32_t a_base = abuf + (wm + lrow) * A_ROWB + lcol8 * 2;
        const uint32_t b_base = bbuf + lrow * B_ROWB + (wn + lcol8) * 2;

        #pragma unroll
        for (int ks = 0; ks < 2; ks++) {
            uint32_t af[2][4];
            #pragma unroll
            for (int mt = 0; mt < 2; mt++)
                LDSM_X4(af[mt], a_base + mt * 16 * A_ROWB + ks * 32);
            uint32_t bf[4][4];
            #pragma unroll
            for (int ng = 0; ng < 4; ng++)
                LDSM_X4T(bf[ng], b_base + ks * 16 * B_ROWB + ng * 32);
            #pragma unroll
            for (int mt = 0; mt < 2; mt++)
                #pragma unroll
                for (int ng = 0; ng < 4; ng++) {
                    mma_f16(acc[mt][2*ng],   af[mt], bf[ng][0], bf[ng][1]);
                    mma_f16(acc[mt][2*ng+1], af[mt], bf[ng][2], bf[ng][3]);
                }
        }
        __syncthreads();
    }

    // ---- epilogue ----
    const int g = lane >> 2, tig = lane & 3;
    #pragma unroll
    for (int mt = 0; mt < 2; mt++) {
        const int r0 = m0 + wm + mt * 16 + g;
        #pragma unroll
        for (int nt = 0; nt < 8; nt++) {
            const int c = n0 + wn + nt * 8 + (tig << 1);
            const float b0 = __ldg(bias + c);
            const float b1 = __ldg(bias + c + 1);
            if (EPI == 0) {
                __half* Ch = (__half*)Cv;
                __half2 v0 = __floats2half2_rn(gelu_tanh(acc[mt][nt][0] + b0),
                                               gelu_tanh(acc[mt][nt][1] + b1));
                __half2 v1 = __floats2half2_rn(gelu_tanh(acc[mt][nt][2] + b0),
                                               gelu_tanh(acc[mt][nt][3] + b1));
                *(__half2*)(Ch + (size_t)r0 * N + c) = v0;
                *(__half2*)(Ch + (size_t)(r0 + 8) * N + c) = v1;
            } else {
                float* Cf = (float*)Cv;
                float2 a0 = *(const float2*)(add + (size_t)r0 * N + c);
                float2 a1 = *(const float2*)(add + (size_t)(r0 + 8) * N + c);
                float2 v0, v1;
                v0.x = acc[mt][nt][0] + b0 + a0.x;
                v0.y = acc[mt][nt][1] + b1 + a0.y;
                v1.x = acc[mt][nt][2] + b0 + a1.x;
                v1.y = acc[mt][nt][3] + b1 + a1.y;
                *(float2*)(Cf + (size_t)r0 * N + c) = v0;
                *(float2*)(Cf + (size_t)(r0 + 8) * N + c) = v1;
            }
        }
    }
}

// ---------------------------------------------------------------------------
extern "C" void kernel_launch(void* const* d_in, const int* in_sizes, int n_in,
                              void* d_out, int out_size)
{
    const float* input    = (const float*)d_in[0];
    const float* residual = (const float*)d_in[1];
    // d_in[2] = residual_norm (unused)
    const float* bias     = (const float*)d_in[3];
    const float* attn_nw  = (const float*)d_in[4];
    const float* attn_nb  = (const float*)d_in[5];
    const float* inter_w  = (const float*)d_in[6];
    const float* inter_b  = (const float*)d_in[7];
    const float* output_w = (const float*)d_in[8];
    const float* output_b = (const float*)d_in[9];
    float* out = (float*)d_out;

    float *p_resadd;
    __half *p_xh, *p_h, *p_w1h, *p_w2h;
    cudaGetSymbolAddress((void**)&p_resadd, g_resadd);
    cudaGetSymbolAddress((void**)&p_xh, g_xh);
    cudaGetSymbolAddress((void**)&p_h, g_h);
    cudaGetSymbolAddress((void**)&p_w1h, g_w1h);
    cudaGetSymbolAddress((void**)&p_w2h, g_w2h);

    cudaFuncSetAttribute(gemm_f16_kernel<0>, cudaFuncAttributeMaxDynamicSharedMemorySize, DSMEM_BYTES);
    cudaFuncSetAttribute(gemm_f16_kernel<1>, cudaFuncAttributeMaxDynamicSharedMemorySize, DSMEM_BYTES);

    // 0) convert weights to fp16 (row-major [K,N] kept — consumed via ldmatrix.trans)
    f2h_kernel<<<(HH * II / 4 + 255) / 256, 256>>>(inter_w,  p_w1h, HH * II / 4);
    f2h_kernel<<<(II * HH / 4 + 255) / 256, 256>>>(output_w, p_w2h, II * HH / 4);

    // 1) fused bias+residual add + LayerNorm -> fp16 x
    fused_add_ln_kernel<<<MM, 256>>>(input, residual, bias, attn_nw, attn_nb);

    // 2) h = fp16(gelu(x @ inter_w + inter_b))   [32768 x 4096]
    gemm_f16_kernel<0><<<dim3(II / BN, MM / BM), 256, DSMEM_BYTES>>>(
        p_xh, p_w1h, inter_b, nullptr, (void*)p_h, HH, II);

    // 3) out = h @ output_w + output_b + resadd   [32768 x 1024]
    gemm_f16_kernel<1><<<dim3(HH / BN, MM / BM), 256, DSMEM_BYTES>>>(
        p_h, p_w2h, output_b, p_resadd, (void*)out, II, HH);
}

// round 12
// speedup vs baseline: 3.0412x; 1.3899x over previous
#include <cuda_runtime.h>
#include <cuda_fp16.h>
#include <cstdint>
#include <math.h>

// Problem dims (fixed by the dataset)
#define MM 32768      // B*S
#define HH 1024
#define II 4096
#define LN_EPS 1e-5f

// Scratch (device globals: allocation-free rule)
__device__ float  g_resadd[(size_t)MM * HH];   // 128 MB fp32 pre-norm sum
__device__ __half g_xh[(size_t)MM * HH];       // 64 MB  fp16 LN output
__device__ __half g_h[(size_t)MM * II];        // 256 MB fp16 gelu output
__device__ __half g_w1h[(size_t)HH * II];      // 8 MB   inter_w  [H,I] fp16 (row-major K,N)
__device__ __half g_w2h[(size_t)II * HH];      // 8 MB   output_w [I,H] fp16 (row-major K,N)

// ---------------------------------------------------------------------------
// helpers
// ---------------------------------------------------------------------------
__device__ __forceinline__ uint32_t smem_u32(const void* p) {
    uint32_t a;
    asm("{ .reg .u64 t; cvta.to.shared.u64 t, %1; cvt.u32.u64 %0, t; }" : "=r"(a) : "l"(p));
    return a;
}
__device__ __forceinline__ float tanh_fast(float x) {
    float y;
    asm("tanh.approx.f32 %0, %1;" : "=f"(y) : "f"(x));
    return y;
}
__device__ __forceinline__ float gelu_tanh(float x) {
    float x3 = x * x * x;
    return 0.5f * x * (1.0f + tanh_fast(0.7978845608028654f * (x + 0.044715f * x3)));
}
__device__ __forceinline__ uint32_t h2_as_u32(__half2 h) {
    uint32_t u;
    *(__half2*)&u = h;
    return u;
}

#define CP_ASYNC16(dst, src) \
    asm volatile("cp.async.cg.shared.global [%0], [%1], 16;\n" :: "r"(dst), "l"(src) : "memory")
#define CP_COMMIT() asm volatile("cp.async.commit_group;\n" ::: "memory")
#define CP_WAIT2()  asm volatile("cp.async.wait_group 2;\n" ::: "memory")

#define LDSM_X4(r, addr) \
    asm volatile("ldmatrix.sync.aligned.m8n8.x4.shared.b16 {%0,%1,%2,%3}, [%4];" \
        : "=r"((r)[0]), "=r"((r)[1]), "=r"((r)[2]), "=r"((r)[3]) : "r"(addr))
#define LDSM_X4T(r, addr) \
    asm volatile("ldmatrix.sync.aligned.m8n8.x4.trans.shared.b16 {%0,%1,%2,%3}, [%4];" \
        : "=r"((r)[0]), "=r"((r)[1]), "=r"((r)[2]), "=r"((r)[3]) : "r"(addr))

__device__ __forceinline__ void mma_f16(float c[4], const uint32_t a[4],
                                        uint32_t b0, uint32_t b1) {
    asm volatile(
        "mma.sync.aligned.m16n8k16.row.col.f32.f16.f16.f32 "
        "{%0,%1,%2,%3}, {%4,%5,%6,%7}, {%8,%9}, {%0,%1,%2,%3};\n"
        : "+f"(c[0]), "+f"(c[1]), "+f"(c[2]), "+f"(c[3])
        : "r"(a[0]), "r"(a[1]), "r"(a[2]), "r"(a[3]), "r"(b0), "r"(b1));
}

// ---------------------------------------------------------------------------
// Kernel 1: resadd = input + bias + residual ; x = fp16(LN(resadd)*g + b)
// ---------------------------------------------------------------------------
__global__ void __launch_bounds__(256) fused_add_ln_kernel(
    const float* __restrict__ inp, const float* __restrict__ resid,
    const float* __restrict__ bias, const float* __restrict__ gamma,
    const float* __restrict__ beta)
{
    const int row = blockIdx.x;
    const int t = threadIdx.x;
    const size_t base = (size_t)row * HH;

    float4 v = ((const float4*)(inp + base))[t];
    float4 r = ((const float4*)(resid + base))[t];
    float4 b = ((const float4*)bias)[t];
    v.x += b.x + r.x; v.y += b.y + r.y; v.z += b.z + r.z; v.w += b.w + r.w;
    ((float4*)(g_resadd + base))[t] = v;

    float s  = v.x + v.y + v.z + v.w;
    float sq = v.x*v.x + v.y*v.y + v.z*v.z + v.w*v.w;
    #pragma unroll
    for (int o = 16; o > 0; o >>= 1) {
        s  += __shfl_xor_sync(0xffffffffu, s,  o);
        sq += __shfl_xor_sync(0xffffffffu, sq, o);
    }
    __shared__ float sh_s[8], sh_q[8];
    const int warp = t >> 5, lane = t & 31;
    if (lane == 0) { sh_s[warp] = s; sh_q[warp] = sq; }
    __syncthreads();
    s = 0.f; sq = 0.f;
    #pragma unroll
    for (int i = 0; i < 8; i++) { s += sh_s[i]; sq += sh_q[i]; }

    const float mu   = s * (1.0f / HH);
    const float var  = sq * (1.0f / HH) - mu * mu;
    const float rstd = rsqrtf(var + LN_EPS);

    float4 gm = ((const float4*)gamma)[t];
    float4 bt = ((const float4*)beta)[t];
    __half2 h0 = __floats2half2_rn((v.x - mu) * rstd * gm.x + bt.x,
                                   (v.y - mu) * rstd * gm.y + bt.y);
    __half2 h1 = __floats2half2_rn((v.z - mu) * rstd * gm.z + bt.z,
                                   (v.w - mu) * rstd * gm.w + bt.w);
    uint2 pk;
    pk.x = h2_as_u32(h0);
    pk.y = h2_as_u32(h1);
    ((uint2*)(g_xh + base))[t] = pk;
}

// ---------------------------------------------------------------------------
// fp32 -> fp16 elementwise convert (weights)
// ---------------------------------------------------------------------------
__global__ void __launch_bounds__(256) f2h_kernel(
    const float* __restrict__ src, __half* __restrict__ dst, int n4)
{
    const int i = blockIdx.x * 256 + threadIdx.x;
    if (i < n4) {
        float4 v = ((const float4*)src)[i];
        uint2 pk;
        pk.x = h2_as_u32(__floats2half2_rn(v.x, v.y));
        pk.y = h2_as_u32(__floats2half2_rn(v.z, v.w));
        ((uint2*)dst)[i] = pk;
    }
}

// ---------------------------------------------------------------------------
// fp16 mma.sync GEMM: C[M,N] = A[M,K] @ B[K,N] (+ epilogue)
// Block tile 128x128, BK=32, 256 threads, 8 warps (4M x 2N), warp tile 32x64.
// 4-stage cp.async pipeline; ldmatrix-fed fragments; fp32 accumulate.
// 2 CTAs/SM (reg-capped at 128 via launch_bounds), single barrier per k-tile.
// EPI==0: C(fp16) = gelu(acc + bias[n])
// EPI==1: C(fp32) = acc + bias[n] + resadd[m,n]
// ---------------------------------------------------------------------------
#define BM 128
#define BN 128
#define BK 32
#define STAGES 4
#define A_ROWB 80                    // 32 halves = 64B data + 16B pad
#define B_ROWB 272                   // 128 halves = 256B data + 16B pad
#define A_BYTES (BM * A_ROWB)        // 10240
#define B_BYTES (BK * B_ROWB)        // 8704
#define STAGE_BYTES (A_BYTES + B_BYTES)   // 18944
#define DSMEM_BYTES (STAGES * STAGE_BYTES)

template <int EPI>
__global__ void __launch_bounds__(256, 2) gemm_f16_kernel(
    const __half* __restrict__ A, const __half* __restrict__ B,
    const float* __restrict__ bias, const float* __restrict__ add,
    void* __restrict__ Cv, int K, int N)
{
    extern __shared__ __align__(128) char dsm[];
    const uint32_t smem = smem_u32(dsm);

    const int t = threadIdx.x;
    const int wid = t >> 5, lane = t & 31;
    const int m0 = blockIdx.y * BM, n0 = blockIdx.x * BN;
    const int wm = (wid & 3) * 32;   // warp row offset
    const int wn = (wid >> 2) * 64;  // warp col offset
    const int KT = K / BK;

    float acc[2][8][4];
    #pragma unroll
    for (int i = 0; i < 2; i++)
        #pragma unroll
        for (int j = 0; j < 8; j++)
            #pragma unroll
            for (int l = 0; l < 4; l++) acc[i][j][l] = 0.f;

    // cp.async staging indices
    const int a_row = t >> 1, a_c = t & 1;        // A: 128 rows x 4 chunks
    const int b_row = t >> 4, b_c = t & 15;       // B: 32 rows x 16 chunks

    auto load_tile = [&](int kt, int stage) {
        const uint32_t abuf = smem + stage * STAGE_BYTES;
        const uint32_t bbuf = abuf + A_BYTES;
        const int k0 = kt * BK;
        // A: 512 chunks of 16B
        #pragma unroll
        for (int j = 0; j < 2; j++) {
            const int c = a_c * 2 + j;
            const uint32_t dst = abuf + a_row * A_ROWB + c * 16;
            const __half* src = A + (size_t)(m0 + a_row) * K + k0 + c * 8;
            CP_ASYNC16(dst, src);
        }
        // B: 512 chunks
        #pragma unroll
        for (int j = 0; j < 2; j++) {
            const int rr = b_row + j * 16;
            const uint32_t dst = bbuf + rr * B_ROWB + b_c * 16;
            const __half* src = B + (size_t)(k0 + rr) * N + n0 + b_c * 8;
            CP_ASYNC16(dst, src);
        }
    };

    // prologue: stages 0..2
    #pragma unroll
    for (int kt = 0; kt < 3; kt++) {
        if (kt < KT) load_tile(kt, kt);
        CP_COMMIT();
    }

    // per-lane ldmatrix base offsets
    const int lrow = lane & 15;          // row within 16-row group
    const int lcol8 = (lane >> 4) * 8;   // 0 or 8 (halves)

    for (int kt = 0; kt < KT; kt++) {
        const int s = kt & 3;
        CP_WAIT2();
        __syncthreads();    // all warps done with iter kt-1; loads for kt landed

        // prefetch tile kt+3 into stage (kt+3)&3 (freed: compute kt-1 done)
        if (kt + 3 < KT) load_tile(kt + 3, (kt + 3) & 3);
        CP_COMMIT();

        const uint32_t abuf = smem + s * STAGE_BYTES;
        const uint32_t bbuf = abuf + A_BYTES;
        const uint32_t a_base = abuf + (wm + lrow) * A_ROWB + lcol8 * 2;
        const uint32_t b_base = bbuf + lrow * B_ROWB + (wn + lcol8) * 2;

        #pragma unroll
        for (int ks = 0; ks < 2; ks++) {
            uint32_t af[2][4];
            #pragma unroll
            for (int mt = 0; mt < 2; mt++)
                LDSM_X4(af[mt], a_base + mt * 16 * A_ROWB + ks * 32);
            uint32_t bf[4][4];
            #pragma unroll
            for (int ng = 0; ng < 4; ng++)
                LDSM_X4T(bf[ng], b_base + ks * 16 * B_ROWB + ng * 32);
            #pragma unroll
            for (int mt = 0; mt < 2; mt++)
                #pragma unroll
                for (int ng = 0; ng < 4; ng++) {
                    mma_f16(acc[mt][2*ng],   af[mt], bf[ng][0], bf[ng][1]);
                    mma_f16(acc[mt][2*ng+1], af[mt], bf[ng][2], bf[ng][3]);
                }
        }
        // no bottom barrier: next iteration's top barrier orders buffer reuse
    }

    // ---- epilogue ----
    const int g = lane >> 2, tig = lane & 3;
    #pragma unroll
    for (int mt = 0; mt < 2; mt++) {
        const int r0 = m0 + wm + mt * 16 + g;
        #pragma unroll
        for (int nt = 0; nt < 8; nt++) {
            const int c = n0 + wn + nt * 8 + (tig << 1);
            const float b0 = __ldg(bias + c);
            const float b1 = __ldg(bias + c + 1);
            if (EPI == 0) {
                __half* Ch = (__half*)Cv;
                __half2 v0 = __floats2half2_rn(gelu_tanh(acc[mt][nt][0] + b0),
                                               gelu_tanh(acc[mt][nt][1] + b1));
                __half2 v1 = __floats2half2_rn(gelu_tanh(acc[mt][nt][2] + b0),
                                               gelu_tanh(acc[mt][nt][3] + b1));
                *(__half2*)(Ch + (size_t)r0 * N + c) = v0;
                *(__half2*)(Ch + (size_t)(r0 + 8) * N + c) = v1;
            } else {
                float* Cf = (float*)Cv;
                float2 a0 = *(const float2*)(add + (size_t)r0 * N + c);
                float2 a1 = *(const float2*)(add + (size_t)(r0 + 8) * N + c);
                float2 v0, v1;
                v0.x = acc[mt][nt][0] + b0 + a0.x;
                v0.y = acc[mt][nt][1] + b1 + a0.y;
                v1.x = acc[mt][nt][2] + b0 + a1.x;
                v1.y = acc[mt][nt][3] + b1 + a1.y;
                *(float2*)(Cf + (size_t)r0 * N + c) = v0;
                *(float2*)(Cf + (size_t)(r0 + 8) * N + c) = v1;
            }
        }
    }
}

// ---------------------------------------------------------------------------
extern "C" void kernel_launch(void* const* d_in, const int* in_sizes, int n_in,
                              void* d_out, int out_size)
{
    const float* input    = (const float*)d_in[0];
    const float* residual = (const float*)d_in[1];
    // d_in[2] = residual_norm (unused)
    const float* bias     = (const float*)d_in[3];
    const float* attn_nw  = (const float*)d_in[4];
    const float* attn_nb  = (const float*)d_in[5];
    const float* inter_w  = (const float*)d_in[6];
    const float* inter_b  = (const float*)d_in[7];
    const float* output_w = (const float*)d_in[8];
    const float* output_b = (const float*)d_in[9];
    float* out = (float*)d_out;

    float *p_resadd;
    __half *p_xh, *p_h, *p_w1h, *p_w2h;
    cudaGetSymbolAddress((void**)&p_resadd, g_resadd);
    cudaGetSymbolAddress((void**)&p_xh, g_xh);
    cudaGetSymbolAddress((void**)&p_h, g_h);
    cudaGetSymbolAddress((void**)&p_w1h, g_w1h);
    cudaGetSymbolAddress((void**)&p_w2h, g_w2h);

    cudaFuncSetAttribute(gemm_f16_kernel<0>, cudaFuncAttributeMaxDynamicSharedMemorySize, DSMEM_BYTES);
    cudaFuncSetAttribute(gemm_f16_kernel<1>, cudaFuncAttributeMaxDynamicSharedMemorySize, DSMEM_BYTES);

    // 0) convert weights to fp16 (row-major [K,N] kept — consumed via ldmatrix.trans)
    f2h_kernel<<<(HH * II / 4 + 255) / 256, 256>>>(inter_w,  p_w1h, HH * II / 4);
    f2h_kernel<<<(II * HH / 4 + 255) / 256, 256>>>(output_w, p_w2h, II * HH / 4);

    // 1) fused bias+residual add + LayerNorm -> fp16 x
    fused_add_ln_kernel<<<MM, 256>>>(input, residual, bias, attn_nw, attn_nb);

    // 2) h = fp16(gelu(x @ inter_w + inter_b))   [32768 x 4096]
    gemm_f16_kernel<0><<<dim3(II / BN, MM / BM), 256, DSMEM_BYTES>>>(
        p_xh, p_w1h, inter_b, nullptr, (void*)p_h, HH, II);

    // 3) out = h @ output_w + output_b + resadd   [32768 x 1024]
    gemm_f16_kernel<1><<<dim3(HH / BN, MM / BM), 256, DSMEM_BYTES>>>(
        p_h, p_w2h, output_b, p_resadd, (void*)out, II, HH);
}

// round 16
// speedup vs baseline: 3.2808x; 1.0788x over previous
#include <cuda_runtime.h>
#include <cuda_fp16.h>
#include <cstdint>
#include <math.h>

// Problem dims (fixed by the dataset)
#define MM 32768      // B*S
#define HH 1024
#define II 4096
#define LN_EPS 1e-5f

// Scratch (device globals: allocation-free rule)
__device__ float  g_resadd[(size_t)MM * HH];   // 128 MB fp32 pre-norm sum
__device__ __half g_xh[(size_t)MM * HH];       // 64 MB  fp16 LN output
__device__ __half g_h[(size_t)MM * II];        // 256 MB fp16 gelu output
__device__ __half g_w1h[(size_t)HH * II];      // 8 MB   inter_w  [H,I] fp16 (row-major K,N)
__device__ __half g_w2h[(size_t)II * HH];      // 8 MB   output_w [I,H] fp16 (row-major K,N)

// ---------------------------------------------------------------------------
// helpers
// ---------------------------------------------------------------------------
__device__ __forceinline__ uint32_t smem_u32(const void* p) {
    uint32_t a;
    asm("{ .reg .u64 t; cvta.to.shared.u64 t, %1; cvt.u32.u64 %0, t; }" : "=r"(a) : "l"(p));
    return a;
}
__device__ __forceinline__ float tanh_fast(float x) {
    float y;
    asm("tanh.approx.f32 %0, %1;" : "=f"(y) : "f"(x));
    return y;
}
__device__ __forceinline__ float gelu_tanh(float x) {
    float x3 = x * x * x;
    return 0.5f * x * (1.0f + tanh_fast(0.7978845608028654f * (x + 0.044715f * x3)));
}
__device__ __forceinline__ uint32_t h2_as_u32(__half2 h) {
    uint32_t u;
    *(__half2*)&u = h;
    return u;
}

#define CP_ASYNC16(dst, src) \
    asm volatile("cp.async.cg.shared.global [%0], [%1], 16;\n" :: "r"(dst), "l"(src) : "memory")
#define CP_COMMIT() asm volatile("cp.async.commit_group;\n" ::: "memory")
#define CP_WAIT1()  asm volatile("cp.async.wait_group 1;\n" ::: "memory")

#define LDSM_X4(r, addr) \
    asm volatile("ldmatrix.sync.aligned.m8n8.x4.shared.b16 {%0,%1,%2,%3}, [%4];" \
        : "=r"((r)[0]), "=r"((r)[1]), "=r"((r)[2]), "=r"((r)[3]) : "r"(addr))
#define LDSM_X4T(r, addr) \
    asm volatile("ldmatrix.sync.aligned.m8n8.x4.trans.shared.b16 {%0,%1,%2,%3}, [%4];" \
        : "=r"((r)[0]), "=r"((r)[1]), "=r"((r)[2]), "=r"((r)[3]) : "r"(addr))

__device__ __forceinline__ void mma_f16(float c[4], const uint32_t a[4],
                                        uint32_t b0, uint32_t b1) {
    asm volatile(
        "mma.sync.aligned.m16n8k16.row.col.f32.f16.f16.f32 "
        "{%0,%1,%2,%3}, {%4,%5,%6,%7}, {%8,%9}, {%0,%1,%2,%3};\n"
        : "+f"(c[0]), "+f"(c[1]), "+f"(c[2]), "+f"(c[3])
        : "r"(a[0]), "r"(a[1]), "r"(a[2]), "r"(a[3]), "r"(b0), "r"(b1));
}

// ---------------------------------------------------------------------------
// Kernel 1: resadd = input + bias + residual ; x = fp16(LN(resadd)*g + b)
// ---------------------------------------------------------------------------
__global__ void __launch_bounds__(256) fused_add_ln_kernel(
    const float* __restrict__ inp, const float* __restrict__ resid,
    const float* __restrict__ bias, const float* __restrict__ gamma,
    const float* __restrict__ beta)
{
    const int row = blockIdx.x;
    const int t = threadIdx.x;
    const size_t base = (size_t)row * HH;

    float4 v = ((const float4*)(inp + base))[t];
    float4 r = ((const float4*)(resid + base))[t];
    float4 b = ((const float4*)bias)[t];
    v.x += b.x + r.x; v.y += b.y + r.y; v.z += b.z + r.z; v.w += b.w + r.w;
    ((float4*)(g_resadd + base))[t] = v;

    float s  = v.x + v.y + v.z + v.w;
    float sq = v.x*v.x + v.y*v.y + v.z*v.z + v.w*v.w;
    #pragma unroll
    for (int o = 16; o > 0; o >>= 1) {
        s  += __shfl_xor_sync(0xffffffffu, s,  o);
        sq += __shfl_xor_sync(0xffffffffu, sq, o);
    }
    __shared__ float sh_s[8], sh_q[8];
    const int warp = t >> 5, lane = t & 31;
    if (lane == 0) { sh_s[warp] = s; sh_q[warp] = sq; }
    __syncthreads();
    s = 0.f; sq = 0.f;
    #pragma unroll
    for (int i = 0; i < 8; i++) { s += sh_s[i]; sq += sh_q[i]; }

    const float mu   = s * (1.0f / HH);
    const float var  = sq * (1.0f / HH) - mu * mu;
    const float rstd = rsqrtf(var + LN_EPS);

    float4 gm = ((const float4*)gamma)[t];
    float4 bt = ((const float4*)beta)[t];
    __half2 h0 = __floats2half2_rn((v.x - mu) * rstd * gm.x + bt.x,
                                   (v.y - mu) * rstd * gm.y + bt.y);
    __half2 h1 = __floats2half2_rn((v.z - mu) * rstd * gm.z + bt.z,
                                   (v.w - mu) * rstd * gm.w + bt.w);
    uint2 pk;
    pk.x = h2_as_u32(h0);
    pk.y = h2_as_u32(h1);
    ((uint2*)(g_xh + base))[t] = pk;
}

// ---------------------------------------------------------------------------
// fp32 -> fp16 elementwise convert (weights)
// ---------------------------------------------------------------------------
__global__ void __launch_bounds__(256) f2h_kernel(
    const float* __restrict__ src, __half* __restrict__ dst, int n4)
{
    const int i = blockIdx.x * 256 + threadIdx.x;
    if (i < n4) {
        float4 v = ((const float4*)src)[i];
        uint2 pk;
        pk.x = h2_as_u32(__floats2half2_rn(v.x, v.y));
        pk.y = h2_as_u32(__floats2half2_rn(v.z, v.w));
        ((uint2*)dst)[i] = pk;
    }
}

// ---------------------------------------------------------------------------
// fp16 mma.sync GEMM: C[M,N] = A[M,K] @ B[K,N] (+ epilogue)
// Block tile 128x128, BK=64, 256 threads, 8 warps (4M x 2N), warp tile 32x64.
// 3-stage cp.async pipeline (prefetch distance 2); ldmatrix-fed; fp32 acc.
// 2 CTAs/SM (reg-capped via launch_bounds), ONE barrier per 64-deep k-tile.
// EPI==0: C(fp16) = gelu(acc + bias[n])
// EPI==1: C(fp32) = acc + bias[n] + resadd[m,n]
// ---------------------------------------------------------------------------
#define BM 128
#define BN 128
#define BK 64
#define STAGES 3
#define A_ROWB 144                   // 64 halves = 128B data + 16B pad
#define B_ROWB 272                   // 128 halves = 256B data + 16B pad
#define A_BYTES (BM * A_ROWB)        // 18432
#define B_BYTES (BK * B_ROWB)        // 17408
#define STAGE_BYTES (A_BYTES + B_BYTES)   // 35840
#define DSMEM_BYTES (STAGES * STAGE_BYTES) // 107520

template <int EPI>
__global__ void __launch_bounds__(256, 2) gemm_f16_kernel(
    const __half* __restrict__ A, const __half* __restrict__ B,
    const float* __restrict__ bias, const float* __restrict__ add,
    void* __restrict__ Cv, int K, int N)
{
    extern __shared__ __align__(128) char dsm[];
    const uint32_t smem = smem_u32(dsm);

    const int t = threadIdx.x;
    const int wid = t >> 5, lane = t & 31;
    const int m0 = blockIdx.y * BM, n0 = blockIdx.x * BN;
    const int wm = (wid & 3) * 32;   // warp row offset
    const int wn = (wid >> 2) * 64;  // warp col offset
    const int KT = K / BK;

    float acc[2][8][4];
    #pragma unroll
    for (int i = 0; i < 2; i++)
        #pragma unroll
        for (int j = 0; j < 8; j++)
            #pragma unroll
            for (int l = 0; l < 4; l++) acc[i][j][l] = 0.f;

    auto load_tile = [&](int kt, int stage) {
        const uint32_t abuf = smem + stage * STAGE_BYTES;
        const uint32_t bbuf = abuf + A_BYTES;
        const int k0 = kt * BK;
        // A: 128 rows x 8 chunks of 16B = 1024 chunks; 4 per thread
        #pragma unroll
        for (int j = 0; j < 4; j++) {
            const int q = t + j * 256;
            const int i = q >> 3, c = q & 7;
            const uint32_t dst = abuf + i * A_ROWB + c * 16;
            const __half* src = A + (size_t)(m0 + i) * K + k0 + c * 8;
            CP_ASYNC16(dst, src);
        }
        // B: 64 rows x 16 chunks = 1024 chunks; 4 per thread
        #pragma unroll
        for (int j = 0; j < 4; j++) {
            const int q = t + j * 256;
            const int rr = q >> 4, c = q & 15;
            const uint32_t dst = bbuf + rr * B_ROWB + c * 16;
            const __half* src = B + (size_t)(k0 + rr) * N + n0 + c * 8;
            CP_ASYNC16(dst, src);
        }
    };

    // prologue: stages 0,1
    #pragma unroll
    for (int kt = 0; kt < 2; kt++) {
        if (kt < KT) load_tile(kt, kt);
        CP_COMMIT();
    }

    // per-lane ldmatrix base offsets
    const int lrow = lane & 15;          // row within 16-row group
    const int lcol8 = (lane >> 4) * 8;   // 0 or 8 (halves)

    int stage = 0;
    for (int kt = 0; kt < KT; kt++) {
        CP_WAIT1();
        __syncthreads();    // all warps done with iter kt-1; loads for kt landed

        // prefetch tile kt+2 into stage (kt+2)%3 (freed: compute kt-1 done)
        if (kt + 2 < KT) {
            int ps = stage + 2; if (ps >= STAGES) ps -= STAGES;
            load_tile(kt + 2, ps);
        }
        CP_COMMIT();

        const uint32_t abuf = smem + stage * STAGE_BYTES;
        const uint32_t bbuf = abuf + A_BYTES;
        const uint32_t a_base = abuf + (wm + lrow) * A_ROWB + lcol8 * 2;
        const uint32_t b_base = bbuf + lrow * B_ROWB + (wn + lcol8) * 2;

        #pragma unroll
        for (int ks = 0; ks < 4; ks++) {
            uint32_t af[2][4];
            #pragma unroll
            for (int mt = 0; mt < 2; mt++)
                LDSM_X4(af[mt], a_base + mt * 16 * A_ROWB + ks * 32);
            uint32_t bf[4][4];
            #pragma unroll
            for (int ng = 0; ng < 4; ng++)
                LDSM_X4T(bf[ng], b_base + ks * 16 * B_ROWB + ng * 32);
            #pragma unroll
            for (int mt = 0; mt < 2; mt++)
                #pragma unroll
                for (int ng = 0; ng < 4; ng++) {
                    mma_f16(acc[mt][2*ng],   af[mt], bf[ng][0], bf[ng][1]);
                    mma_f16(acc[mt][2*ng+1], af[mt], bf[ng][2], bf[ng][3]);
                }
        }
        stage = (stage + 1 == STAGES) ? 0 : stage + 1;
        // no bottom barrier: next iteration's top barrier orders buffer reuse
    }

    // ---- epilogue ----
    const int g = lane >> 2, tig = lane & 3;
    #pragma unroll
    for (int mt = 0; mt < 2; mt++) {
        const int r0 = m0 + wm + mt * 16 + g;
        #pragma unroll
        for (int nt = 0; nt < 8; nt++) {
            const int c = n0 + wn + nt * 8 + (tig << 1);
            const float b0 = __ldg(bias + c);
            const float b1 = __ldg(bias + c + 1);
            if (EPI == 0) {
                __half* Ch = (__half*)Cv;
                __half2 v0 = __floats2half2_rn(gelu_tanh(acc[mt][nt][0] + b0),
                                               gelu_tanh(acc[mt][nt][1] + b1));
                __half2 v1 = __floats2half2_rn(gelu_tanh(acc[mt][nt][2] + b0),
                                               gelu_tanh(acc[mt][nt][3] + b1));
                *(__half2*)(Ch + (size_t)r0 * N + c) = v0;
                *(__half2*)(Ch + (size_t)(r0 + 8) * N + c) = v1;
            } else {
                float* Cf = (float*)Cv;
                float2 a0 = *(const float2*)(add + (size_t)r0 * N + c);
                float2 a1 = *(const float2*)(add + (size_t)(r0 + 8) * N + c);
                float2 v0, v1;
                v0.x = acc[mt][nt][0] + b0 + a0.x;
                v0.y = acc[mt][nt][1] + b1 + a0.y;
                v1.x = acc[mt][nt][2] + b0 + a1.x;
                v1.y = acc[mt][nt][3] + b1 + a1.y;
                *(float2*)(Cf + (size_t)r0 * N + c) = v0;
                *(float2*)(Cf + (size_t)(r0 + 8) * N + c) = v1;
            }
        }
    }
}

// ---------------------------------------------------------------------------
extern "C" void kernel_launch(void* const* d_in, const int* in_sizes, int n_in,
                              void* d_out, int out_size)
{
    const float* input    = (const float*)d_in[0];
    const float* residual = (const float*)d_in[1];
    // d_in[2] = residual_norm (unused)
    const float* bias     = (const float*)d_in[3];
    const float* attn_nw  = (const float*)d_in[4];
    const float* attn_nb  = (const float*)d_in[5];
    const float* inter_w  = (const float*)d_in[6];
    const float* inter_b  = (const float*)d_in[7];
    const float* output_w = (const float*)d_in[8];
    const float* output_b = (const float*)d_in[9];
    float* out = (float*)d_out;

    float *p_resadd;
    __half *p_xh, *p_h, *p_w1h, *p_w2h;
    cudaGetSymbolAddress((void**)&p_resadd, g_resadd);
    cudaGetSymbolAddress((void**)&p_xh, g_xh);
    cudaGetSymbolAddress((void**)&p_h, g_h);
    cudaGetSymbolAddress((void**)&p_w1h, g_w1h);
    cudaGetSymbolAddress((void**)&p_w2h, g_w2h);

    cudaFuncSetAttribute(gemm_f16_kernel<0>, cudaFuncAttributeMaxDynamicSharedMemorySize, DSMEM_BYTES);
    cudaFuncSetAttribute(gemm_f16_kernel<1>, cudaFuncAttributeMaxDynamicSharedMemorySize, DSMEM_BYTES);

    // 0) convert weights to fp16 (row-major [K,N] kept — consumed via ldmatrix.trans)
    f2h_kernel<<<(HH * II / 4 + 255) / 256, 256>>>(inter_w,  p_w1h, HH * II / 4);
    f2h_kernel<<<(II * HH / 4 + 255) / 256, 256>>>(output_w, p_w2h, II * HH / 4);

    // 1) fused bias+residual add + LayerNorm -> fp16 x
    fused_add_ln_kernel<<<MM, 256>>>(input, residual, bias, attn_nw, attn_nb);

    // 2) h = fp16(gelu(x @ inter_w + inter_b))   [32768 x 4096]
    gemm_f16_kernel<0><<<dim3(II / BN, MM / BM), 256, DSMEM_BYTES>>>(
        p_xh, p_w1h, inter_b, nullptr, (void*)p_h, HH, II);

    // 3) out = h @ output_w + output_b + resadd   [32768 x 1024]
    gemm_f16_kernel<1><<<dim3(HH / BN, MM / BM), 256, DSMEM_BYTES>>>(
        p_h, p_w2h, output_b, p_resadd, (void*)out, II, HH);
}

// round 17
// speedup vs baseline: 3.3355x; 1.0167x over previous
#include <cuda_runtime.h>
#include <cuda_fp16.h>
#include <cstdint>
#include <math.h>

// Problem dims (fixed by the dataset)
#define MM 32768      // B*S
#define HH 1024
#define II 4096
#define LN_EPS 1e-5f

// Scratch (device globals: allocation-free rule)
__device__ float  g_resadd[(size_t)MM * HH];   // 128 MB fp32 pre-norm sum
__device__ __half g_xh[(size_t)MM * HH];       // 64 MB  fp16 LN output
__device__ __half g_h[(size_t)MM * II];        // 256 MB fp16 gelu output
__device__ __half g_w1h[(size_t)HH * II];      // 8 MB   inter_w  [H,I] fp16 (row-major K,N)
__device__ __half g_w2h[(size_t)II * HH];      // 8 MB   output_w [I,H] fp16 (row-major K,N)

// ---------------------------------------------------------------------------
// helpers
// ---------------------------------------------------------------------------
__device__ __forceinline__ uint32_t smem_u32(const void* p) {
    uint32_t a;
    asm("{ .reg .u64 t; cvta.to.shared.u64 t, %1; cvt.u32.u64 %0, t; }" : "=r"(a) : "l"(p));
    return a;
}
__device__ __forceinline__ float tanh_fast(float x) {
    float y;
    asm("tanh.approx.f32 %0, %1;" : "=f"(y) : "f"(x));
    return y;
}
__device__ __forceinline__ float gelu_tanh(float x) {
    float x3 = x * x * x;
    return 0.5f * x * (1.0f + tanh_fast(0.7978845608028654f * (x + 0.044715f * x3)));
}
__device__ __forceinline__ uint32_t h2_as_u32(__half2 h) {
    uint32_t u;
    *(__half2*)&u = h;
    return u;
}

#define CP_ASYNC16(dst, src) \
    asm volatile("cp.async.cg.shared.global [%0], [%1], 16;\n" :: "r"(dst), "l"(src) : "memory")

// cp.async completion -> mbarrier arrive (counts 1 against init count; .noinc)
#define CP_ASYNC_MBAR_ARRIVE(mbar) \
    asm volatile("cp.async.mbarrier.arrive.noinc.shared::cta.b64 [%0];" :: "r"(mbar) : "memory")

#define MBARRIER_INIT(addr, cnt) \
    asm volatile("mbarrier.init.shared.b64 [%0], %1;" :: "r"(addr), "r"(cnt) : "memory")
#define MBARRIER_ARRIVE(addr) \
    asm volatile("mbarrier.arrive.shared.b64 _, [%0];" :: "r"(addr) : "memory")
// wait until phase `ph` of the mbarrier is no longer pending (acquire)
#define MBAR_WAIT(addr, ph) do { \
    uint32_t _done = 0; \
    while (!_done) { \
        asm volatile("{\n\t.reg .pred p;\n\t" \
            "mbarrier.try_wait.parity.acquire.cta.shared::cta.b64 p, [%1], %2, 0x989680;\n\t" \
            "selp.b32 %0, 1, 0, p;\n\t}" \
            : "=r"(_done) : "r"(addr), "r"(ph) : "memory"); \
    } \
} while (0)

#define LDSM_X4(r, addr) \
    asm volatile("ldmatrix.sync.aligned.m8n8.x4.shared.b16 {%0,%1,%2,%3}, [%4];" \
        : "=r"((r)[0]), "=r"((r)[1]), "=r"((r)[2]), "=r"((r)[3]) : "r"(addr))
#define LDSM_X4T(r, addr) \
    asm volatile("ldmatrix.sync.aligned.m8n8.x4.trans.shared.b16 {%0,%1,%2,%3}, [%4];" \
        : "=r"((r)[0]), "=r"((r)[1]), "=r"((r)[2]), "=r"((r)[3]) : "r"(addr))

__device__ __forceinline__ void mma_f16(float c[4], const uint32_t a[4],
                                        uint32_t b0, uint32_t b1) {
    asm volatile(
        "mma.sync.aligned.m16n8k16.row.col.f32.f16.f16.f32 "
        "{%0,%1,%2,%3}, {%4,%5,%6,%7}, {%8,%9}, {%0,%1,%2,%3};\n"
        : "+f"(c[0]), "+f"(c[1]), "+f"(c[2]), "+f"(c[3])
        : "r"(a[0]), "r"(a[1]), "r"(a[2]), "r"(a[3]), "r"(b0), "r"(b1));
}

// ---------------------------------------------------------------------------
// Kernel 1: resadd = input + bias + residual ; x = fp16(LN(resadd)*g + b)
// ---------------------------------------------------------------------------
__global__ void __launch_bounds__(256) fused_add_ln_kernel(
    const float* __restrict__ inp, const float* __restrict__ resid,
    const float* __restrict__ bias, const float* __restrict__ gamma,
    const float* __restrict__ beta)
{
    const int row = blockIdx.x;
    const int t = threadIdx.x;
    const size_t base = (size_t)row * HH;

    float4 v = ((const float4*)(inp + base))[t];
    float4 r = ((const float4*)(resid + base))[t];
    float4 b = ((const float4*)bias)[t];
    v.x += b.x + r.x; v.y += b.y + r.y; v.z += b.z + r.z; v.w += b.w + r.w;
    ((float4*)(g_resadd + base))[t] = v;

    float s  = v.x + v.y + v.z + v.w;
    float sq = v.x*v.x + v.y*v.y + v.z*v.z + v.w*v.w;
    #pragma unroll
    for (int o = 16; o > 0; o >>= 1) {
        s  += __shfl_xor_sync(0xffffffffu, s,  o);
        sq += __shfl_xor_sync(0xffffffffu, sq, o);
    }
    __shared__ float sh_s[8], sh_q[8];
    const int warp = t >> 5, lane = t & 31;
    if (lane == 0) { sh_s[warp] = s; sh_q[warp] = sq; }
    __syncthreads();
    s = 0.f; sq = 0.f;
    #pragma unroll
    for (int i = 0; i < 8; i++) { s += sh_s[i]; sq += sh_q[i]; }

    const float mu   = s * (1.0f / HH);
    const float var  = sq * (1.0f / HH) - mu * mu;
    const float rstd = rsqrtf(var + LN_EPS);

    float4 gm = ((const float4*)gamma)[t];
    float4 bt = ((const float4*)beta)[t];
    __half2 h0 = __floats2half2_rn((v.x - mu) * rstd * gm.x + bt.x,
                                   (v.y - mu) * rstd * gm.y + bt.y);
    __half2 h1 = __floats2half2_rn((v.z - mu) * rstd * gm.z + bt.z,
                                   (v.w - mu) * rstd * gm.w + bt.w);
    uint2 pk;
    pk.x = h2_as_u32(h0);
    pk.y = h2_as_u32(h1);
    ((uint2*)(g_xh + base))[t] = pk;
}

// ---------------------------------------------------------------------------
// fp32 -> fp16 elementwise convert (weights)
// ---------------------------------------------------------------------------
__global__ void __launch_bounds__(256) f2h_kernel(
    const float* __restrict__ src, __half* __restrict__ dst, int n4)
{
    const int i = blockIdx.x * 256 + threadIdx.x;
    if (i < n4) {
        float4 v = ((const float4*)src)[i];
        uint2 pk;
        pk.x = h2_as_u32(__floats2half2_rn(v.x, v.y));
        pk.y = h2_as_u32(__floats2half2_rn(v.z, v.w));
        ((uint2*)dst)[i] = pk;
    }
}

// ---------------------------------------------------------------------------
// fp16 mma.sync GEMM, warp-specialized producer/consumer.
// Block tile 128x128, BK=64. 288 threads: warps 0-7 consumers (4M x 2N,
// warp tile 32x64, ldmatrix+mma only), warp 8 producer (all cp.async).
// 3-stage ring with (full, empty) mbarrier pairs — NO __syncthreads in loop.
// 2 CTAs/SM. EPI==0: C(fp16)=gelu(acc+bias); EPI==1: C(fp32)=acc+bias+add.
// ---------------------------------------------------------------------------
#define BM 128
#define BN 128
#define BK 64
#define STAGES 3
#define A_ROWB 144                   // 64 halves = 128B data + 16B pad
#define B_ROWB 272                   // 128 halves = 256B data + 16B pad
#define A_BYTES (BM * A_ROWB)        // 18432
#define B_BYTES (BK * B_ROWB)        // 17408
#define STAGE_BYTES (A_BYTES + B_BYTES)   // 35840
#define DSMEM_BYTES (STAGES * STAGE_BYTES) // 107520
#define NTHREADS 288

template <int EPI>
__global__ void __launch_bounds__(NTHREADS, 2) gemm_f16_kernel(
    const __half* __restrict__ A, const __half* __restrict__ B,
    const float* __restrict__ bias, const float* __restrict__ add,
    void* __restrict__ Cv, int K, int N)
{
    extern __shared__ __align__(128) char dsm[];
    __shared__ __align__(8) uint64_t s_full[STAGES], s_empty[STAGES];

    const uint32_t smem = smem_u32(dsm);
    const uint32_t full0  = smem_u32(&s_full[0]);
    const uint32_t empty0 = smem_u32(&s_empty[0]);

    const int t = threadIdx.x;
    const int wid = t >> 5, lane = t & 31;
    const int m0 = blockIdx.y * BM, n0 = blockIdx.x * BN;
    const int KT = K / BK;

    if (t == 0) {
        #pragma unroll
        for (int s = 0; s < STAGES; s++) {
            MBARRIER_INIT(full0 + 8 * s, 32);    // producer warp: 32 cp-completion arrives
            MBARRIER_INIT(empty0 + 8 * s, 256);  // 8 consumer warps arrive
        }
    }
    __syncthreads();

    if (wid == 8) {
        // ---------------- producer warp ----------------
        int stage = 0, phase = 1;   // first pass over each stage: empty by construction
        for (int kt = 0; kt < KT; kt++) {
            MBAR_WAIT(empty0 + 8 * stage, (uint32_t)phase);
            const uint32_t abuf = smem + stage * STAGE_BYTES;
            const uint32_t bbuf = abuf + A_BYTES;
            const int k0 = kt * BK;
            // A: 128 rows x 8 chunks(16B) = 1024 chunks; 32 per lane
            #pragma unroll
            for (int j = 0; j < 32; j++) {
                const int q = lane + j * 32;
                const int i = q >> 3, c = q & 7;
                CP_ASYNC16(abuf + i * A_ROWB + c * 16,
                           A + (size_t)(m0 + i) * K + k0 + c * 8);
            }
            // B: 64 rows x 16 chunks = 1024 chunks; 32 per lane
            #pragma unroll
            for (int j = 0; j < 32; j++) {
                const int q = lane + j * 32;
                const int rr = q >> 4, c = q & 15;
                CP_ASYNC16(bbuf + rr * B_ROWB + c * 16,
                           B + (size_t)(k0 + rr) * N + n0 + c * 8);
            }
            CP_ASYNC_MBAR_ARRIVE(full0 + 8 * stage);
            if (++stage == STAGES) { stage = 0; phase ^= 1; }
        }
        return;
    }

    // ---------------- consumer warps (wid 0-7) ----------------
    const int wm = (wid & 3) * 32;   // warp row offset
    const int wn = (wid >> 2) * 64;  // warp col offset

    float acc[2][8][4];
    #pragma unroll
    for (int i = 0; i < 2; i++)
        #pragma unroll
        for (int j = 0; j < 8; j++)
            #pragma unroll
            for (int l = 0; l < 4; l++) acc[i][j][l] = 0.f;

    const int lrow = lane & 15;          // row within 16-row group
    const int lcol8 = (lane >> 4) * 8;   // 0 or 8 (halves)

    int stage = 0, phase = 0;
    for (int kt = 0; kt < KT; kt++) {
        MBAR_WAIT(full0 + 8 * stage, (uint32_t)phase);

        const uint32_t abuf = smem + stage * STAGE_BYTES;
        const uint32_t bbuf = abuf + A_BYTES;
        const uint32_t a_base = abuf + (wm + lrow) * A_ROWB + lcol8 * 2;
        const uint32_t b_base = bbuf + lrow * B_ROWB + (wn + lcol8) * 2;

        #pragma unroll
        for (int ks = 0; ks < 4; ks++) {
            uint32_t af[2][4];
            #pragma unroll
            for (int mt = 0; mt < 2; mt++)
                LDSM_X4(af[mt], a_base + mt * 16 * A_ROWB + ks * 32);
            uint32_t bf[4][4];
            #pragma unroll
            for (int ng = 0; ng < 4; ng++)
                LDSM_X4T(bf[ng], b_base + ks * 16 * B_ROWB + ng * 32);
            #pragma unroll
            for (int mt = 0; mt < 2; mt++)
                #pragma unroll
                for (int ng = 0; ng < 4; ng++) {
                    mma_f16(acc[mt][2*ng],   af[mt], bf[ng][0], bf[ng][1]);
                    mma_f16(acc[mt][2*ng+1], af[mt], bf[ng][2], bf[ng][3]);
                }
        }
        MBARRIER_ARRIVE(empty0 + 8 * stage);
        if (++stage == STAGES) { stage = 0; phase ^= 1; }
    }

    // ---- epilogue ----
    const int g = lane >> 2, tig = lane & 3;
    #pragma unroll
    for (int mt = 0; mt < 2; mt++) {
        const int r0 = m0 + wm + mt * 16 + g;
        #pragma unroll
        for (int nt = 0; nt < 8; nt++) {
            const int c = n0 + wn + nt * 8 + (tig << 1);
            const float b0 = __ldg(bias + c);
            const float b1 = __ldg(bias + c + 1);
            if (EPI == 0) {
                __half* Ch = (__half*)Cv;
                __half2 v0 = __floats2half2_rn(gelu_tanh(acc[mt][nt][0] + b0),
                                               gelu_tanh(acc[mt][nt][1] + b1));
                __half2 v1 = __floats2half2_rn(gelu_tanh(acc[mt][nt][2] + b0),
                                               gelu_tanh(acc[mt][nt][3] + b1));
                *(__half2*)(Ch + (size_t)r0 * N + c) = v0;
                *(__half2*)(Ch + (size_t)(r0 + 8) * N + c) = v1;
            } else {
                float* Cf = (float*)Cv;
                float2 a0 = *(const float2*)(add + (size_t)r0 * N + c);
                float2 a1 = *(const float2*)(add + (size_t)(r0 + 8) * N + c);
                float2 v0, v1;
                v0.x = acc[mt][nt][0] + b0 + a0.x;
                v0.y = acc[mt][nt][1] + b1 + a0.y;
                v1.x = acc[mt][nt][2] + b0 + a1.x;
                v1.y = acc[mt][nt][3] + b1 + a1.y;
                *(float2*)(Cf + (size_t)r0 * N + c) = v0;
                *(float2*)(Cf + (size_t)(r0 + 8) * N + c) = v1;
            }
        }
    }
}

// ---------------------------------------------------------------------------
extern "C" void kernel_launch(void* const* d_in, const int* in_sizes, int n_in,
                              void* d_out, int out_size)
{
    const float* input    = (const float*)d_in[0];
    const float* residual = (const float*)d_in[1];
    // d_in[2] = residual_norm (unused)
    const float* bias     = (const float*)d_in[3];
    const float* attn_nw  = (const float*)d_in[4];
    const float* attn_nb  = (const float*)d_in[5];
    const float* inter_w  = (const float*)d_in[6];
    const float* inter_b  = (const float*)d_in[7];
    const float* output_w = (const float*)d_in[8];
    const float* output_b = (const float*)d_in[9];
    float* out = (float*)d_out;

    float *p_resadd;
    __half *p_xh, *p_h, *p_w1h, *p_w2h;
    cudaGetSymbolAddress((void**)&p_resadd, g_resadd);
    cudaGetSymbolAddress((void**)&p_xh, g_xh);
    cudaGetSymbolAddress((void**)&p_h, g_h);
    cudaGetSymbolAddress((void**)&p_w1h, g_w1h);
    cudaGetSymbolAddress((void**)&p_w2h, g_w2h);

    cudaFuncSetAttribute(gemm_f16_kernel<0>, cudaFuncAttributeMaxDynamicSharedMemorySize, DSMEM_BYTES);
    cudaFuncSetAttribute(gemm_f16_kernel<1>, cudaFuncAttributeMaxDynamicSharedMemorySize, DSMEM_BYTES);

    // 0) convert weights to fp16 (row-major [K,N] kept — consumed via ldmatrix.trans)
    f2h_kernel<<<(HH * II / 4 + 255) / 256, 256>>>(inter_w,  p_w1h, HH * II / 4);
    f2h_kernel<<<(II * HH / 4 + 255) / 256, 256>>>(output_w, p_w2h, II * HH / 4);

    // 1) fused bias+residual add + LayerNorm -> fp16 x
    fused_add_ln_kernel<<<MM, 256>>>(input, residual, bias, attn_nw, attn_nb);

    // 2) h = fp16(gelu(x @ inter_w + inter_b))   [32768 x 4096]
    gemm_f16_kernel<0><<<dim3(II / BN, MM / BM), NTHREADS, DSMEM_BYTES>>>(
        p_xh, p_w1h, inter_b, nullptr, (void*)p_h, HH, II);

    // 3) out = h @ output_w + output_b + resadd   [32768 x 1024]
    gemm_f16_kernel<1><<<dim3(HH / BN, MM / BM), NTHREADS, DSMEM_BYTES>>>(
        p_h, p_w2h, output_b, p_resadd, (void*)out, II, HH);
}